// round 2
// baseline (speedup 1.0000x reference)
#include <cuda_runtime.h>
#include <cuda_bf16.h>
#include <cstdint>

#define EMB_DIM   128
#define N_FEATS   9
#define NUM_LAYER 5
#define MAX_NODES 50000
#define MAX_EDGES 800000

// ---------------- scratch (no allocations allowed) ----------------
static __device__ float g_h0[MAX_NODES * EMB_DIM];
static __device__ float g_h1[MAX_NODES * EMB_DIM];
static __device__ float g_agg[MAX_NODES * EMB_DIM];

// ---------------- encode: h[n] = sum_f atom_emb[f][x[n][f]] ----------------
__global__ void encode_kernel(const int* __restrict__ x,
                              const float* __restrict__ emb,
                              float* __restrict__ h, int N)
{
    int t = blockIdx.x * blockDim.x + threadIdx.x;
    int n = t >> 5;
    int lane = t & 31;
    if (n >= N) return;
    float4 acc = make_float4(0.f, 0.f, 0.f, 0.f);
#pragma unroll
    for (int f = 0; f < N_FEATS; f++) {
        unsigned idx = (unsigned)x[(size_t)n * N_FEATS + f];
        if (idx >= 128u) idx = 0u;   // safety clamp
        const float4* p = (const float4*)(emb + ((size_t)f * 128 + idx) * EMB_DIM) + lane;
        float4 v = *p;
        acc.x += v.x; acc.y += v.y; acc.z += v.z; acc.w += v.w;
    }
    *(((float4*)(h + (size_t)n * EMB_DIM)) + lane) = acc;
}

// ---------------- zero ----------------
__global__ void zero_kernel(float4* __restrict__ p, int n4)
{
    int t = blockIdx.x * blockDim.x + threadIdx.x;
    if (t < n4) p[t] = make_float4(0.f, 0.f, 0.f, 0.f);
}

// ---------------- scatter-add: agg[dst] += h[src], one warp per edge ----------------
__global__ void scatter_kernel(const int* __restrict__ ei,
                               const float* __restrict__ h,
                               float* __restrict__ agg, int E, int N)
{
    int t = blockIdx.x * blockDim.x + threadIdx.x;
    int e = t >> 5;
    int lane = t & 31;
    if (e >= E) return;
    unsigned src = (unsigned)ei[e];
    unsigned dst = (unsigned)ei[(size_t)E + e];
    if (src >= (unsigned)N || dst >= (unsigned)N) return;  // safety guard
    float4 v = *(((const float4*)(h + (size_t)src * EMB_DIM)) + lane);
    float* p = agg + (size_t)dst * EMB_DIM + lane * 4;
    asm volatile("red.global.add.v4.f32 [%0], {%1,%2,%3,%4};"
                 :: "l"(p), "f"(v.x), "f"(v.y), "f"(v.z), "f"(v.w)
                 : "memory");
}

// ---------------- fused GEMM: out = A@Wr + H@Wt + b ----------------
// 512 threads, persistent blocks, both 128x128 weights resident in SMEM.
// Tile = 64 rows x 128 cols. warp w -> rows 4w..4w+3, lane -> cols 4*lane..4*lane+3.
#define GEMM_THREADS 512
#define ROWS_TILE    64
// smem floats: Wr 16384 + Wt 16384 + A 8192 + H 8192 + b 128 = 49280 (197120 B)
#define GEMM_SMEM_FLOATS 49280

__global__ __launch_bounds__(GEMM_THREADS)
void gemm_kernel(const float* __restrict__ A,
                 const float* __restrict__ H,
                 const float* __restrict__ Wr,
                 const float* __restrict__ Wt,
                 const float* __restrict__ bias,
                 float* __restrict__ out, int N)
{
    extern __shared__ float sm[];
    float* sWr = sm;                 // [128][128]
    float* sWt = sm + 16384;         // [128][128]
    float* sA  = sm + 32768;         // [64][128]
    float* sH  = sA + 8192;          // [64][128]
    float* sb  = sH + 8192;          // [128]

    const int tid  = threadIdx.x;
    const int lane = tid & 31;
    const int warp = tid >> 5;       // 0..15

    // load weights once (float4)
    {
        const float4* gWr = (const float4*)Wr;
        const float4* gWt = (const float4*)Wt;
        float4* lWr = (float4*)sWr;
        float4* lWt = (float4*)sWt;
        for (int i = tid; i < 4096; i += GEMM_THREADS) {
            lWr[i] = gWr[i];
            lWt[i] = gWt[i];
        }
        if (tid < 128) sb[tid] = bias[tid];
    }

    const int numTiles = (N + ROWS_TILE - 1) / ROWS_TILE;

    for (int tile = blockIdx.x; tile < numTiles; tile += gridDim.x) {
        const int row0 = tile * ROWS_TILE;
        __syncthreads();   // protect sA/sH from previous iteration's readers

        // load A/H tile: 64 rows x 32 float4
        for (int i = tid; i < ROWS_TILE * 32; i += GEMM_THREADS) {
            int r  = i >> 5;
            int c4 = i & 31;
            int gr = row0 + r;
            float4 av, hv;
            if (gr < N) {
                av = ((const float4*)(A + (size_t)gr * EMB_DIM))[c4];
                hv = ((const float4*)(H + (size_t)gr * EMB_DIM))[c4];
            } else {
                av = make_float4(0.f, 0.f, 0.f, 0.f);
                hv = av;
            }
            ((float4*)sA)[i] = av;
            ((float4*)sH)[i] = hv;
        }
        __syncthreads();

        float4 acc[4];
#pragma unroll
        for (int r = 0; r < 4; r++) acc[r] = make_float4(0.f, 0.f, 0.f, 0.f);

        const int rbase = warp * 4;

#pragma unroll 1
        for (int k0 = 0; k0 < EMB_DIM; k0 += 4) {
            float4 a4[4], h4[4];
#pragma unroll
            for (int r = 0; r < 4; r++) {
                a4[r] = *(const float4*)&sA[(rbase + r) * EMB_DIM + k0];
                h4[r] = *(const float4*)&sH[(rbase + r) * EMB_DIM + k0];
            }
#pragma unroll
            for (int kk = 0; kk < 4; kk++) {
                float4 wr = *(const float4*)&sWr[(k0 + kk) * EMB_DIM + lane * 4];
                float4 wt = *(const float4*)&sWt[(k0 + kk) * EMB_DIM + lane * 4];
#pragma unroll
                for (int r = 0; r < 4; r++) {
                    float a  = ((const float*)&a4[r])[kk];
                    float hh = ((const float*)&h4[r])[kk];
                    acc[r].x = fmaf(a, wr.x, acc[r].x);
                    acc[r].y = fmaf(a, wr.y, acc[r].y);
                    acc[r].z = fmaf(a, wr.z, acc[r].z);
                    acc[r].w = fmaf(a, wr.w, acc[r].w);
                    acc[r].x = fmaf(hh, wt.x, acc[r].x);
                    acc[r].y = fmaf(hh, wt.y, acc[r].y);
                    acc[r].z = fmaf(hh, wt.z, acc[r].z);
                    acc[r].w = fmaf(hh, wt.w, acc[r].w);
                }
            }
        }

        // epilogue: + bias, store
        float4 b4 = *(const float4*)&sb[lane * 4];
#pragma unroll
        for (int r = 0; r < 4; r++) {
            int gr = row0 + rbase + r;
            if (gr < N) {
                float4 o;
                o.x = acc[r].x + b4.x;
                o.y = acc[r].y + b4.y;
                o.z = acc[r].z + b4.z;
                o.w = acc[r].w + b4.w;
                ((float4*)(out + (size_t)gr * EMB_DIM))[lane] = o;
            }
        }
    }
}

// ---------------- launch ----------------
extern "C" void kernel_launch(void* const* d_in, const int* in_sizes, int n_in,
                              void* d_out, int out_size)
{
    const int* x          = (const int*)d_in[0];         // [N,9] int32 (JAX x64 disabled)
    const int* ei         = (const int*)d_in[1];         // [2,E] int32
    // d_in[2] edge_attr: unused by the reference
    const float* atom_emb = (const float*)d_in[3];       // [9,128,128]
    const float* W_rel    = (const float*)d_in[4];       // [5,128,128]
    const float* b_rel    = (const float*)d_in[5];       // [5,128]
    const float* W_root   = (const float*)d_in[6];       // [5,128,128]
    float* out = (float*)d_out;

    const int N = in_sizes[0] / N_FEATS;
    const int E = in_sizes[1] / 2;

    float *h0, *h1, *agg;
    cudaGetSymbolAddress((void**)&h0, g_h0);
    cudaGetSymbolAddress((void**)&h1, g_h1);
    cudaGetSymbolAddress((void**)&agg, g_agg);

    cudaFuncSetAttribute(gemm_kernel,
                         cudaFuncAttributeMaxDynamicSharedMemorySize,
                         GEMM_SMEM_FLOATS * sizeof(float));

    // encode -> h0
    {
        int threads = 256;
        int blocks = (N * 32 + threads - 1) / threads;
        encode_kernel<<<blocks, threads>>>(x, atom_emb, h0, N);
    }

    const int n4 = N * EMB_DIM / 4;
    const int zblocks = (n4 + 255) / 256;
    const int sblocks = (E * 32 + 255) / 256;
    const int gemm_grid = 148;   // persistent CTAs

    float* hcur = h0;
    float* hnxt = h1;
    for (int l = 0; l < NUM_LAYER; l++) {
        zero_kernel<<<zblocks, 256>>>((float4*)agg, n4);
        scatter_kernel<<<sblocks, 256>>>(ei, hcur, agg, E, N);
        float* dst = (l == NUM_LAYER - 1) ? out : hnxt;
        gemm_kernel<<<gemm_grid, GEMM_THREADS, GEMM_SMEM_FLOATS * sizeof(float)>>>(
            agg, hcur, W_rel + (size_t)l * 16384, W_root + (size_t)l * 16384,
            b_rel + (size_t)l * 128, dst, N);
        float* tmp = hcur; hcur = hnxt; hnxt = tmp;
    }
}

// round 3
// speedup vs baseline: 1.5336x; 1.5336x over previous
#include <cuda_runtime.h>
#include <cuda_bf16.h>
#include <cstdint>

#define EMB_DIM   128
#define N_FEATS   9
#define NUM_LAYER 5
#define MAX_NODES 50000
#define MAX_EDGES 800000

// ---------------- scratch (no allocations allowed) ----------------
static __device__ float g_h0[MAX_NODES * EMB_DIM];
static __device__ float g_h1[MAX_NODES * EMB_DIM];
static __device__ float g_agg[MAX_NODES * EMB_DIM];
static __device__ int   g_deg[MAX_NODES];
static __device__ int   g_rowptr[MAX_NODES + 1];
static __device__ int   g_cursor[MAX_NODES];
static __device__ int   g_esrc[MAX_EDGES];

// ---------------- encode: h[n] = sum_f atom_emb[f][x[n][f]] ----------------
__global__ void encode_kernel(const int* __restrict__ x,
                              const float* __restrict__ emb,
                              float* __restrict__ h, int N)
{
    int t = blockIdx.x * blockDim.x + threadIdx.x;
    int n = t >> 5;
    int lane = t & 31;
    if (n >= N) return;
    float4 acc = make_float4(0.f, 0.f, 0.f, 0.f);
#pragma unroll
    for (int f = 0; f < N_FEATS; f++) {
        unsigned idx = (unsigned)x[(size_t)n * N_FEATS + f];
        if (idx >= 128u) idx = 0u;
        const float4* p = (const float4*)(emb + ((size_t)f * 128 + idx) * EMB_DIM) + lane;
        float4 v = *p;
        acc.x += v.x; acc.y += v.y; acc.z += v.z; acc.w += v.w;
    }
    *(((float4*)(h + (size_t)n * EMB_DIM)) + lane) = acc;
}

// ---------------- CSR build ----------------
__global__ void zero_deg_kernel(int* __restrict__ deg, int N)
{
    int i = blockIdx.x * blockDim.x + threadIdx.x;
    if (i < N) deg[i] = 0;
}

__global__ void hist_kernel(const int* __restrict__ ei, int* __restrict__ deg,
                            int E, int N)
{
    int e = blockIdx.x * blockDim.x + threadIdx.x;
    if (e >= E) return;
    unsigned dst = (unsigned)ei[(size_t)E + e];
    if (dst < (unsigned)N) atomicAdd(&deg[dst], 1);
}

// single-block scan: rowptr[i+1] = incl_prefix(deg), cursor[i] = excl_prefix
__global__ __launch_bounds__(1024)
void scan_kernel(const int* __restrict__ deg, int* __restrict__ rowptr,
                 int* __restrict__ cursor, int N)
{
    __shared__ int warp_sums[32];
    const int tid  = threadIdx.x;
    const int lane = tid & 31;
    const int wid  = tid >> 5;
    if (tid == 0) rowptr[0] = 0;
    int running = 0;
    for (int base = 0; base < N; base += 1024) {
        int i = base + tid;
        int v = (i < N) ? deg[i] : 0;
        int x = v;
#pragma unroll
        for (int o = 1; o < 32; o <<= 1) {
            int y = __shfl_up_sync(0xFFFFFFFFu, x, o);
            if (lane >= o) x += y;
        }
        if (lane == 31) warp_sums[wid] = x;
        __syncthreads();
        if (wid == 0) {
            int w = warp_sums[lane];
#pragma unroll
            for (int o = 1; o < 32; o <<= 1) {
                int y = __shfl_up_sync(0xFFFFFFFFu, w, o);
                if (lane >= o) w += y;
            }
            warp_sums[lane] = w;
        }
        __syncthreads();
        int incl  = x + (wid > 0 ? warp_sums[wid - 1] : 0);
        int total = warp_sums[31];
        if (i < N) {
            rowptr[i + 1] = running + incl;
            cursor[i]     = running + incl - v;
        }
        running += total;
        __syncthreads();
    }
}

__global__ void fill_kernel(const int* __restrict__ ei, int* __restrict__ cursor,
                            int* __restrict__ esrc, int E, int N)
{
    int e = blockIdx.x * blockDim.x + threadIdx.x;
    if (e >= E) return;
    unsigned src = (unsigned)ei[e];
    unsigned dst = (unsigned)ei[(size_t)E + e];
    if (src >= (unsigned)N || dst >= (unsigned)N) return;
    int pos = atomicAdd(&cursor[dst], 1);
    esrc[pos] = (int)src;
}

// ---------------- gather aggregate: agg[n] = sum_{e in adj(n)} h[esrc[e]] ----
__global__ void gather_kernel(const int* __restrict__ rowptr,
                              const int* __restrict__ esrc,
                              const float* __restrict__ h,
                              float* __restrict__ agg, int N)
{
    int t = blockIdx.x * blockDim.x + threadIdx.x;
    int n = t >> 5;
    int lane = t & 31;
    if (n >= N) return;
    int beg = rowptr[n];
    int end = rowptr[n + 1];
    float4 acc0 = make_float4(0.f, 0.f, 0.f, 0.f);
    float4 acc1 = make_float4(0.f, 0.f, 0.f, 0.f);
    int e = beg;
    for (; e + 1 < end; e += 2) {
        int s0 = __ldg(&esrc[e]);
        int s1 = __ldg(&esrc[e + 1]);
        float4 v0 = *(((const float4*)(h + (size_t)s0 * EMB_DIM)) + lane);
        float4 v1 = *(((const float4*)(h + (size_t)s1 * EMB_DIM)) + lane);
        acc0.x += v0.x; acc0.y += v0.y; acc0.z += v0.z; acc0.w += v0.w;
        acc1.x += v1.x; acc1.y += v1.y; acc1.z += v1.z; acc1.w += v1.w;
    }
    if (e < end) {
        int s0 = __ldg(&esrc[e]);
        float4 v0 = *(((const float4*)(h + (size_t)s0 * EMB_DIM)) + lane);
        acc0.x += v0.x; acc0.y += v0.y; acc0.z += v0.z; acc0.w += v0.w;
    }
    float4 o;
    o.x = acc0.x + acc1.x; o.y = acc0.y + acc1.y;
    o.z = acc0.z + acc1.z; o.w = acc0.w + acc1.w;
    *(((float4*)(agg + (size_t)n * EMB_DIM)) + lane) = o;
}

// ---------------- fused GEMM: out = A@Wr + H@Wt + b ----------------
// 256 threads = 8 warps. Tile = 64 rows x 128 cols.
// warp w -> rows 8w..8w+7 (warp-uniform => broadcast LDS for A/H).
// lane  -> cols 4*lane..4*lane+3.
#define GEMM_THREADS 256
#define ROWS_TILE    64
#define ROWS_PER_WARP 8
// smem floats: Wr 16384 + Wt 16384 + A 8192 + H 8192 + b 128 = 49280 (197120 B)
#define GEMM_SMEM_FLOATS 49280

__global__ __launch_bounds__(GEMM_THREADS, 1)
void gemm_kernel(const float* __restrict__ A,
                 const float* __restrict__ H,
                 const float* __restrict__ Wr,
                 const float* __restrict__ Wt,
                 const float* __restrict__ bias,
                 float* __restrict__ out, int N)
{
    extern __shared__ float sm[];
    float* sWr = sm;                 // [128][128]
    float* sWt = sm + 16384;         // [128][128]
    float* sA  = sm + 32768;         // [64][128]
    float* sH  = sA + 8192;          // [64][128]
    float* sb  = sH + 8192;          // [128]

    const int tid  = threadIdx.x;
    const int lane = tid & 31;
    const int warp = tid >> 5;       // 0..7

    // load weights once (float4)
    {
        const float4* gWr = (const float4*)Wr;
        const float4* gWt = (const float4*)Wt;
        float4* lWr = (float4*)sWr;
        float4* lWt = (float4*)sWt;
        for (int i = tid; i < 4096; i += GEMM_THREADS) {
            lWr[i] = gWr[i];
            lWt[i] = gWt[i];
        }
        if (tid < 128) sb[tid] = bias[tid];
    }

    const int numTiles = (N + ROWS_TILE - 1) / ROWS_TILE;
    const int rbase = warp * ROWS_PER_WARP;
    const int c4 = lane;             // float4 column index

    for (int tile = blockIdx.x; tile < numTiles; tile += gridDim.x) {
        const int row0 = tile * ROWS_TILE;
        __syncthreads();   // protect sA/sH from previous iteration's readers

        // load A/H tile: 64 rows x 32 float4 => 2048 float4, 8 per thread
        for (int i = tid; i < ROWS_TILE * 32; i += GEMM_THREADS) {
            int r  = i >> 5;
            int cc = i & 31;
            int gr = row0 + r;
            float4 av, hv;
            if (gr < N) {
                av = ((const float4*)(A + (size_t)gr * EMB_DIM))[cc];
                hv = ((const float4*)(H + (size_t)gr * EMB_DIM))[cc];
            } else {
                av = make_float4(0.f, 0.f, 0.f, 0.f);
                hv = av;
            }
            ((float4*)sA)[i] = av;
            ((float4*)sH)[i] = hv;
        }
        __syncthreads();

        float4 acc[ROWS_PER_WARP];
#pragma unroll
        for (int r = 0; r < ROWS_PER_WARP; r++)
            acc[r] = make_float4(0.f, 0.f, 0.f, 0.f);

#pragma unroll 1
        for (int k0 = 0; k0 < EMB_DIM; k0 += 4) {
            // ---- A @ Wr phase ----
            {
                float4 s[ROWS_PER_WARP];
#pragma unroll
                for (int r = 0; r < ROWS_PER_WARP; r++)
                    s[r] = *(const float4*)&sA[(rbase + r) * EMB_DIM + k0];
#pragma unroll
                for (int kk = 0; kk < 4; kk++) {
                    float4 w = *(const float4*)&sWr[(k0 + kk) * EMB_DIM + c4 * 4];
#pragma unroll
                    for (int r = 0; r < ROWS_PER_WARP; r++) {
                        float a = ((const float*)&s[r])[kk];
                        acc[r].x = fmaf(a, w.x, acc[r].x);
                        acc[r].y = fmaf(a, w.y, acc[r].y);
                        acc[r].z = fmaf(a, w.z, acc[r].z);
                        acc[r].w = fmaf(a, w.w, acc[r].w);
                    }
                }
            }
            // ---- H @ Wt phase ----
            {
                float4 s[ROWS_PER_WARP];
#pragma unroll
                for (int r = 0; r < ROWS_PER_WARP; r++)
                    s[r] = *(const float4*)&sH[(rbase + r) * EMB_DIM + k0];
#pragma unroll
                for (int kk = 0; kk < 4; kk++) {
                    float4 w = *(const float4*)&sWt[(k0 + kk) * EMB_DIM + c4 * 4];
#pragma unroll
                    for (int r = 0; r < ROWS_PER_WARP; r++) {
                        float hh = ((const float*)&s[r])[kk];
                        acc[r].x = fmaf(hh, w.x, acc[r].x);
                        acc[r].y = fmaf(hh, w.y, acc[r].y);
                        acc[r].z = fmaf(hh, w.z, acc[r].z);
                        acc[r].w = fmaf(hh, w.w, acc[r].w);
                    }
                }
            }
        }

        // epilogue: + bias, store
        float4 b4 = *(const float4*)&sb[c4 * 4];
#pragma unroll
        for (int r = 0; r < ROWS_PER_WARP; r++) {
            int gr = row0 + rbase + r;
            if (gr < N) {
                float4 o;
                o.x = acc[r].x + b4.x;
                o.y = acc[r].y + b4.y;
                o.z = acc[r].z + b4.z;
                o.w = acc[r].w + b4.w;
                ((float4*)(out + (size_t)gr * EMB_DIM))[c4] = o;
            }
        }
    }
}

// ---------------- launch ----------------
extern "C" void kernel_launch(void* const* d_in, const int* in_sizes, int n_in,
                              void* d_out, int out_size)
{
    const int* x          = (const int*)d_in[0];         // [N,9] int32
    const int* ei         = (const int*)d_in[1];         // [2,E] int32
    // d_in[2] edge_attr: unused by the reference
    const float* atom_emb = (const float*)d_in[3];       // [9,128,128]
    const float* W_rel    = (const float*)d_in[4];       // [5,128,128]
    const float* b_rel    = (const float*)d_in[5];       // [5,128]
    const float* W_root   = (const float*)d_in[6];       // [5,128,128]
    float* out = (float*)d_out;

    const int N = in_sizes[0] / N_FEATS;
    const int E = in_sizes[1] / 2;

    float *h0, *h1, *agg;
    int *deg, *rowptr, *cursor, *esrc;
    cudaGetSymbolAddress((void**)&h0, g_h0);
    cudaGetSymbolAddress((void**)&h1, g_h1);
    cudaGetSymbolAddress((void**)&agg, g_agg);
    cudaGetSymbolAddress((void**)&deg, g_deg);
    cudaGetSymbolAddress((void**)&rowptr, g_rowptr);
    cudaGetSymbolAddress((void**)&cursor, g_cursor);
    cudaGetSymbolAddress((void**)&esrc, g_esrc);

    cudaFuncSetAttribute(gemm_kernel,
                         cudaFuncAttributeMaxDynamicSharedMemorySize,
                         GEMM_SMEM_FLOATS * sizeof(float));

    // encode -> h0
    {
        int threads = 256;
        int blocks = (N * 32 + threads - 1) / threads;
        encode_kernel<<<blocks, threads>>>(x, atom_emb, h0, N);
    }

    // CSR build (once per call)
    zero_deg_kernel<<<(N + 255) / 256, 256>>>(deg, N);
    hist_kernel<<<(E + 255) / 256, 256>>>(ei, deg, E, N);
    scan_kernel<<<1, 1024>>>(deg, rowptr, cursor, N);
    fill_kernel<<<(E + 255) / 256, 256>>>(ei, cursor, esrc, E, N);

    const int gblocks = (N * 32 + 255) / 256;
    const int gemm_grid = 148;

    float* hcur = h0;
    float* hnxt = h1;
    for (int l = 0; l < NUM_LAYER; l++) {
        gather_kernel<<<gblocks, 256>>>(rowptr, esrc, hcur, agg, N);
        float* dst = (l == NUM_LAYER - 1) ? out : hnxt;
        gemm_kernel<<<gemm_grid, GEMM_THREADS, GEMM_SMEM_FLOATS * sizeof(float)>>>(
            agg, hcur, W_rel + (size_t)l * 16384, W_root + (size_t)l * 16384,
            b_rel + (size_t)l * 128, dst, N);
        float* tmp = hcur; hcur = hnxt; hnxt = tmp;
    }
}